// round 15
// baseline (speedup 1.0000x reference)
#include <cuda_runtime.h>
#include <cuda_bf16.h>
#include <cstdint>
#include <math.h>

#define NN 1024
#define NP 16
#define NB 2048
#define SSZ 18433
#define NEU_OFF 1025
#define PEP_OFF 2049
#define DTc (1.0f/120.0f)

// bf16 scratch operands for the GEMM (device globals: no allocations)
__device__ __nv_bfloat16 g_Abf[(size_t)NB * NN];   // firing, bf16
__device__ __nv_bfloat16 g_Bbf[(size_t)NN * NN];   // synapse, bf16

// ---------------------------------------------------------------------------
// Kernel 1 (R11-exact): 512-thread blocks, 2 per batch row (grid 4096).
// Block handles 16 torus rows + 2 halo rows in SMEM transposed [p][row*32+c]
// (stride 578). rt/lf via warp shuffle. Aligned float4 slab I/O.
// Neuron slot written pre-multiplied by ablate; k2 atomicAdds DT*C*abl.
// ---------------------------------------------------------------------------
#define K1T 512
#define HSTR 578            // 18 rows * 32 + 2 pad

extern "C" __global__ void __launch_bounds__(K1T)
k1_kernel(const float* __restrict__ u, const float* __restrict__ state,
          const float* __restrict__ noise_u, const float* __restrict__ D,
          const float* __restrict__ prodr, const float* __restrict__ decayr,
          const float* __restrict__ act, const float* __restrict__ ndec,
          const float* __restrict__ inl, const float* __restrict__ syn,
          float* __restrict__ out_f, float* __restrict__ snew)
{
    extern __shared__ float s[];            // 16 * 578 floats (~37 KB)
    __shared__ float sD[16], sP[16], sDe[16], sA[16];
    const int tid  = threadIdx.x;
    const int bid  = blockIdx.x;
    const int b    = bid >> 1;              // batch row
    const int half = bid & 1;               // which 512-neuron half
    const int n0   = half * 512;            // first neuron of this block
    const int r0   = half * 16;             // first torus row

    // Folded synapse conversion: half a row per block for bid < 2048.
    if (bid < 2 * NN) {
        int row = bid >> 1;
        size_t i = (size_t)row * NN + (bid & 1) * 512 + tid;
        g_Bbf[i] = __float2bfloat16_rn(syn[i]);
    }

    if (tid < 16) {
        sD[tid]  = fabsf(D[tid]);
        sP[tid]  = fabsf(prodr[tid]);
        sDe[tid] = fabsf(decayr[tid]);
        sA[tid]  = act[tid];
    }
    const float* __restrict__ srow = state + (size_t)b * SSZ;
    float* __restrict__ drow = snew + (size_t)b * SSZ;

    // --- Stage this block's 8192-element slab region as aligned float4 ---
    const int gbase = 8192 * half;
    const int h  = (4 - ((b + 1) & 3)) & 3;
    const int t4 = (4 - h) & 3;
    const int N4 = (8192 - h - t4) >> 2;

    if (tid < h) {
        int l = tid;
        s[(l & 15) * HSTR + 32 + (l >> 4)] = __ldcs(srow + PEP_OFF + gbase + l);
    }
    if (tid < t4) {
        int l = 8192 - t4 + tid;
        s[(l & 15) * HSTR + 32 + (l >> 4)] = __ldcs(srow + PEP_OFF + gbase + l);
    }
    {
        const float4* __restrict__ src4 =
            (const float4*)(srow + PEP_OFF + gbase + h);
        #pragma unroll
        for (int i = tid; i < N4; i += K1T) {
            float4 v = __ldcs(src4 + i);
            int l = h + 4 * i;
            s[((l + 0) & 15) * HSTR + 32 + ((l + 0) >> 4)] = v.x;
            s[((l + 1) & 15) * HSTR + 32 + ((l + 1) >> 4)] = v.y;
            s[((l + 2) & 15) * HSTR + 32 + ((l + 2) >> 4)] = v.z;
            s[((l + 3) & 15) * HSTR + 32 + ((l + 3) >> 4)] = v.w;
        }
    }
    // --- Halo rows ---
    {
        int rlo = (r0 + 31) & 31;
        int g = 16 * (rlo * 32) + tid;
        s[(tid & 15) * HSTR + 0 * 32 + (tid >> 4)] = __ldcs(srow + PEP_OFF + g);
        int rhi = (r0 + 16) & 31;
        int g2 = 16 * (rhi * 32) + tid;
        s[(tid & 15) * HSTR + 17 * 32 + (tid >> 4)] = __ldcs(srow + PEP_OFF + g2);
    }

    // Neuron-level elementwise work
    const int n = n0 + tid;
    const int lane = tid & 31;
    float abl = srow[n];
    float neu = srow[NEU_OFF + n];
    float nz  = noise_u[(size_t)b * NN + n];
    float nm  = neu * abl;
    float f   = fmaxf(neu, 0.0f) * abl;
    f = -(f + 0.01f) * log1pf(-nz);
    f = fminf(fmaxf(f, 0.0f), 10.0f);
    out_f[(size_t)b * NN + n] = f;
    g_Abf[(size_t)b * NN + n] = __float2bfloat16_rn(f);
    drow[n] = abl;
    float pc2 = __ldg(srow + NN);
    if (tid == 0 && half == 0) drow[NN] = pc2;
    float ub  = __ldg(u + b);
    float ndv = fabsf(__ldg(ndec));
    float il  = inl[n];

    __syncthreads();

    const int r_loc = tid >> 5;
    const int i_up = (r_loc + 2) * 32 + lane;
    const int i_dn = r_loc * 32 + lane;
    const int i_ct = (r_loc + 1) * 32 + lane;
    const int lrt = (lane + 1)  & 31;
    const int llf = (lane + 31) & 31;

    float ctr[16];
    #pragma unroll
    for (int p = 0; p < 16; p++) ctr[p] = s[p * HSTR + i_ct];

    float psum = 0.0f;
    #pragma unroll
    for (int p = 0; p < 16; p++) {
        const float* sp = s + p * HSTR;
        float up = sp[i_up];
        float dn = sp[i_dn];
        float rt = __shfl_sync(0xffffffffu, ctr[p], lrt);
        float lf = __shfl_sync(0xffffffffu, ctr[p], llf);
        float lap = up + dn + rt + lf - 4.0f * ctr[p];
        psum += ctr[p] * sA[p];
        float d = sP[p] * f - sDe[p] * ctr[p] + sD[p] * lap;
        ctr[p] = fmaf(d, DTc, ctr[p]);
    }
    float dn_part = psum * pc2 - nm * ndv + il * ub;
    // Pre-multiplied by ablate; k2 atomically adds DT*C*abl.
    drow[NEU_OFF + n] = (nm + dn_part * DTc) * abl;

    __syncthreads();
    #pragma unroll
    for (int p = 0; p < 16; p++) s[p * HSTR + i_ct] = ctr[p];
    __syncthreads();

    // --- Write back slab region ---
    if (tid < h) {
        int l = tid;
        __stcs(drow + PEP_OFF + gbase + l, s[(l & 15) * HSTR + 32 + (l >> 4)]);
    }
    if (tid < t4) {
        int l = 8192 - t4 + tid;
        __stcs(drow + PEP_OFF + gbase + l, s[(l & 15) * HSTR + 32 + (l >> 4)]);
    }
    {
        float4* __restrict__ dst4 = (float4*)(drow + PEP_OFF + gbase + h);
        #pragma unroll
        for (int i = tid; i < N4; i += K1T) {
            int l = h + 4 * i;
            float4 v;
            v.x = s[((l + 0) & 15) * HSTR + 32 + ((l + 0) >> 4)];
            v.y = s[((l + 1) & 15) * HSTR + 32 + ((l + 1) >> 4)];
            v.z = s[((l + 2) & 15) * HSTR + 32 + ((l + 2) >> 4)];
            v.w = s[((l + 3) & 15) * HSTR + 32 + ((l + 3) >> 4)];
            __stcs(dst4 + i, v);
        }
    }
}

// ---------------------------------------------------------------------------
// Kernel 2: split-K bf16 GEMM, KSPLIT=4. Grid (16, 32, 4) = 2048 CTAs.
// Each CTA: BM=64 x BN=64 tile over a K quarter (4 k64-tiles), 128 threads,
// 4 warps (2m x 2n), 2-stage cp.async (32 KB smem -> 7 CTAs/SM resident).
// Epilogue: atomicAdd(DT * C_part * ablate) into the pre-scaled neuron slot.
// ---------------------------------------------------------------------------
#define BM 64
#define BN 64
#define BKH 64
#define KSPLIT 4
#define KITERS (NN / BKH / KSPLIT)   // 4
#define STAGES 2

#define A_TILE_BYTES (BM * BKH * 2)   // 8192
#define B_TILE_BYTES (BKH * BN * 2)   // 8192
#define SMEM_K2 (STAGES * (A_TILE_BYTES + B_TILE_BYTES))  // 32768

__device__ __forceinline__ void cpa16(uint32_t s, const void* g) {
    asm volatile("cp.async.cg.shared.global [%0], [%1], 16;" :: "r"(s), "l"(g));
}
#define CP_COMMIT() asm volatile("cp.async.commit_group;")
#define CP_WAIT(n)  asm volatile("cp.async.wait_group %0;" :: "n"(n))

__device__ __forceinline__ void ldsm4(uint32_t& r0, uint32_t& r1, uint32_t& r2,
                                      uint32_t& r3, uint32_t a) {
    asm volatile("ldmatrix.sync.aligned.m8n8.x4.shared.b16 {%0,%1,%2,%3}, [%4];"
                 : "=r"(r0), "=r"(r1), "=r"(r2), "=r"(r3) : "r"(a));
}
__device__ __forceinline__ void ldsm4t(uint32_t& r0, uint32_t& r1, uint32_t& r2,
                                       uint32_t& r3, uint32_t a) {
    asm volatile("ldmatrix.sync.aligned.m8n8.x4.trans.shared.b16 {%0,%1,%2,%3}, [%4];"
                 : "=r"(r0), "=r"(r1), "=r"(r2), "=r"(r3) : "r"(a));
}
__device__ __forceinline__ void mma16(float* c, const uint32_t* a, const uint32_t* b) {
    asm volatile(
        "mma.sync.aligned.m16n8k16.row.col.f32.bf16.bf16.f32 "
        "{%0,%1,%2,%3}, {%4,%5,%6,%7}, {%8,%9}, {%0,%1,%2,%3};"
        : "+f"(c[0]), "+f"(c[1]), "+f"(c[2]), "+f"(c[3])
        : "r"(a[0]), "r"(a[1]), "r"(a[2]), "r"(a[3]), "r"(b[0]), "r"(b[1]));
}

__device__ __forceinline__ uint32_t swz(int row, int c) {
    return (uint32_t)(row * 128 + ((c ^ (row & 7)) << 4));
}

extern "C" __global__ void __launch_bounds__(128)
k2_gemm(const float* __restrict__ state, float* __restrict__ snew)
{
    extern __shared__ __align__(16) unsigned char dsm[];
    const uint32_t sbase = (uint32_t)__cvta_generic_to_shared(dsm);
    const uint32_t sA = sbase;                          // [STAGES][A_TILE_BYTES]
    const uint32_t sB = sbase + STAGES * A_TILE_BYTES;  // [STAGES][B_TILE_BYTES]

    const int tid  = threadIdx.x;
    const int lane = tid & 31;
    const int warp = tid >> 5;
    const int wm = warp >> 1, wn = warp & 1;
    const int l15 = lane & 15, l16 = lane >> 4;
    const int m0 = blockIdx.y * BM;
    const int n0 = blockIdx.x * BN;
    const int k0 = blockIdx.z * (NN / KSPLIT);    // K quarter base

    const __nv_bfloat16* __restrict__ gA = g_Abf;
    const __nv_bfloat16* __restrict__ gB = g_Bbf;

    const int sr = tid >> 3;     // 0..15
    const int sc = tid & 7;      // 16B chunk within 128B row

    float acc[2][4][4];
    #pragma unroll
    for (int i = 0; i < 2; i++)
        #pragma unroll
        for (int j = 0; j < 4; j++)
            #pragma unroll
            for (int k = 0; k < 4; k++) acc[i][j][k] = 0.0f;

    auto stage = [&](int kt) {
        const int buf = kt & 1;
        const int kh = k0 + kt * BKH;
        uint32_t aB = sA + buf * A_TILE_BYTES;
        #pragma unroll
        for (int i = 0; i < 4; i++) {
            int row = sr + i * 16;
            cpa16(aB + swz(row, sc), gA + (size_t)(m0 + row) * NN + kh + sc * 8);
        }
        uint32_t bB = sB + buf * B_TILE_BYTES;
        #pragma unroll
        for (int i = 0; i < 4; i++) {
            int row = sr + i * 16;
            cpa16(bB + swz(row, sc), gB + (size_t)(kh + row) * NN + n0 + sc * 8);
        }
    };

    stage(0); CP_COMMIT();

    for (int kt = 0; kt < KITERS; kt++) {
        CP_WAIT(0);
        __syncthreads();                 // buffer kt&1 ready; prev reads done

        if (kt + 1 < KITERS) { stage(kt + 1); CP_COMMIT(); }

        const int cur = kt & 1;
        const uint32_t aB = sA + cur * A_TILE_BYTES;
        const uint32_t bB = sB + cur * B_TILE_BYTES;

        #pragma unroll
        for (int s = 0; s < 4; s++) {               // 4 k16 steps per BK=64
            uint32_t a[2][4];
            #pragma unroll
            for (int sm = 0; sm < 2; sm++) {
                int row = wm * 32 + sm * 16 + l15;
                int ch  = 2 * s + l16;
                ldsm4(a[sm][0], a[sm][1], a[sm][2], a[sm][3], aB + swz(row, ch));
            }
            uint32_t bq[2][4];
            #pragma unroll
            for (int nt = 0; nt < 2; nt++) {
                int row = 16 * s + l15;
                int ch  = wn * 4 + nt * 2 + l16;
                ldsm4t(bq[nt][0], bq[nt][1], bq[nt][2], bq[nt][3], bB + swz(row, ch));
            }
            #pragma unroll
            for (int sm = 0; sm < 2; sm++)
                #pragma unroll
                for (int j = 0; j < 4; j++) {
                    uint32_t bp[2] = { bq[j >> 1][(j & 1) * 2],
                                       bq[j >> 1][(j & 1) * 2 + 1] };
                    mma16(acc[sm][j], a[sm], bp);
                }
        }
        __syncthreads();                 // all reads of cur done before restage
    }

    // ---- split-K epilogue: atomicAdd(DT * C_part * ablate) ----
    const int g = lane >> 2, t = lane & 3;
    #pragma unroll
    for (int sm = 0; sm < 2; sm++) {
        #pragma unroll
        for (int j = 0; j < 4; j++) {
            int row0 = m0 + wm * 32 + sm * 16 + g;
            int col0 = n0 + wn * 32 + j * 8 + 2 * t;
            #pragma unroll
            for (int hh = 0; hh < 2; hh++) {
                int m = row0 + hh * 8;
                size_t off = (size_t)m * SSZ;
                #pragma unroll
                for (int q = 0; q < 2; q++) {
                    int nn = col0 + q;
                    float cc  = acc[sm][j][hh * 2 + q];
                    float abl = state[off + nn];
                    atomicAdd(snew + off + NEU_OFF + nn, DTc * cc * abl);
                }
            }
        }
    }
}

// ---------------------------------------------------------------------------
extern "C" void kernel_launch(void* const* d_in, const int* in_sizes, int n_in,
                              void* d_out, int out_size) {
    const float* u      = (const float*)d_in[0];
    const float* state  = (const float*)d_in[1];
    const float* noise  = (const float*)d_in[2];
    const float* D      = (const float*)d_in[3];
    const float* prodr  = (const float*)d_in[4];
    const float* decayr = (const float*)d_in[5];
    const float* act    = (const float*)d_in[6];
    const float* syn    = (const float*)d_in[7];
    const float* ndec   = (const float*)d_in[8];
    const float* inl    = (const float*)d_in[9];

    float* out   = (float*)d_out;
    float* out_f = out;                         // firing [2048,1024]
    float* snew  = out + (size_t)NB * NN;       // state_new [2048,18433]

    const int smem1 = 16 * HSTR * sizeof(float);
    cudaFuncSetAttribute(k1_kernel, cudaFuncAttributeMaxDynamicSharedMemorySize, smem1);
    k1_kernel<<<2 * NB, K1T, smem1>>>(u, state, noise, D, prodr, decayr, act,
                                      ndec, inl, syn, out_f, snew);

    cudaFuncSetAttribute(k2_gemm, cudaFuncAttributeMaxDynamicSharedMemorySize, SMEM_K2);
    dim3 grid(NN / BN, NB / BM, KSPLIT);
    k2_gemm<<<grid, 128, SMEM_K2>>>(state, snew);
}

// round 17
// speedup vs baseline: 1.0821x; 1.0821x over previous
#include <cuda_runtime.h>
#include <cuda_bf16.h>
#include <cstdint>
#include <math.h>

#define NN 1024
#define NP 16
#define NB 2048
#define SSZ 18433
#define NEU_OFF 1025
#define PEP_OFF 2049
#define DTc (1.0f/120.0f)

// bf16 scratch operands for the GEMM (device globals: no allocations)
__device__ __nv_bfloat16 g_Abf[(size_t)NB * NN];   // firing, bf16
__device__ __nv_bfloat16 g_Bbf[(size_t)NN * NN];   // synapse, bf16

// ---------------------------------------------------------------------------
// Kernel 1 (R11-exact): 512-thread blocks, 2 per batch row (grid 4096).
// Block handles 16 torus rows + 2 halo rows in SMEM transposed [p][row*32+c]
// (stride 578). rt/lf via warp shuffle. Aligned float4 slab I/O.
// Neuron slot written pre-multiplied by ablate; k2 atomicAdds DT*C*abl.
// ---------------------------------------------------------------------------
#define K1T 512
#define HSTR 578            // 18 rows * 32 + 2 pad

extern "C" __global__ void __launch_bounds__(K1T)
k1_kernel(const float* __restrict__ u, const float* __restrict__ state,
          const float* __restrict__ noise_u, const float* __restrict__ D,
          const float* __restrict__ prodr, const float* __restrict__ decayr,
          const float* __restrict__ act, const float* __restrict__ ndec,
          const float* __restrict__ inl, const float* __restrict__ syn,
          float* __restrict__ out_f, float* __restrict__ snew)
{
    extern __shared__ float s[];            // 16 * 578 floats (~37 KB)
    __shared__ float sD[16], sP[16], sDe[16], sA[16];
    const int tid  = threadIdx.x;
    const int bid  = blockIdx.x;
    const int b    = bid >> 1;              // batch row
    const int half = bid & 1;               // which 512-neuron half
    const int n0   = half * 512;            // first neuron of this block
    const int r0   = half * 16;             // first torus row

    // Folded synapse conversion: half a row per block for bid < 2048.
    if (bid < 2 * NN) {
        int row = bid >> 1;
        size_t i = (size_t)row * NN + (bid & 1) * 512 + tid;
        g_Bbf[i] = __float2bfloat16_rn(syn[i]);
    }

    if (tid < 16) {
        sD[tid]  = fabsf(D[tid]);
        sP[tid]  = fabsf(prodr[tid]);
        sDe[tid] = fabsf(decayr[tid]);
        sA[tid]  = act[tid];
    }
    const float* __restrict__ srow = state + (size_t)b * SSZ;
    float* __restrict__ drow = snew + (size_t)b * SSZ;

    // --- Stage this block's 8192-element slab region as aligned float4 ---
    const int gbase = 8192 * half;
    const int h  = (4 - ((b + 1) & 3)) & 3;
    const int t4 = (4 - h) & 3;
    const int N4 = (8192 - h - t4) >> 2;

    if (tid < h) {
        int l = tid;
        s[(l & 15) * HSTR + 32 + (l >> 4)] = __ldcs(srow + PEP_OFF + gbase + l);
    }
    if (tid < t4) {
        int l = 8192 - t4 + tid;
        s[(l & 15) * HSTR + 32 + (l >> 4)] = __ldcs(srow + PEP_OFF + gbase + l);
    }
    {
        const float4* __restrict__ src4 =
            (const float4*)(srow + PEP_OFF + gbase + h);
        #pragma unroll
        for (int i = tid; i < N4; i += K1T) {
            float4 v = __ldcs(src4 + i);
            int l = h + 4 * i;
            s[((l + 0) & 15) * HSTR + 32 + ((l + 0) >> 4)] = v.x;
            s[((l + 1) & 15) * HSTR + 32 + ((l + 1) >> 4)] = v.y;
            s[((l + 2) & 15) * HSTR + 32 + ((l + 2) >> 4)] = v.z;
            s[((l + 3) & 15) * HSTR + 32 + ((l + 3) >> 4)] = v.w;
        }
    }
    // --- Halo rows ---
    {
        int rlo = (r0 + 31) & 31;
        int g = 16 * (rlo * 32) + tid;
        s[(tid & 15) * HSTR + 0 * 32 + (tid >> 4)] = __ldcs(srow + PEP_OFF + g);
        int rhi = (r0 + 16) & 31;
        int g2 = 16 * (rhi * 32) + tid;
        s[(tid & 15) * HSTR + 17 * 32 + (tid >> 4)] = __ldcs(srow + PEP_OFF + g2);
    }

    // Neuron-level elementwise work
    const int n = n0 + tid;
    const int lane = tid & 31;
    float abl = srow[n];
    float neu = srow[NEU_OFF + n];
    float nz  = noise_u[(size_t)b * NN + n];
    float nm  = neu * abl;
    float f   = fmaxf(neu, 0.0f) * abl;
    f = -(f + 0.01f) * log1pf(-nz);
    f = fminf(fmaxf(f, 0.0f), 10.0f);
    out_f[(size_t)b * NN + n] = f;
    g_Abf[(size_t)b * NN + n] = __float2bfloat16_rn(f);
    drow[n] = abl;
    float pc2 = __ldg(srow + NN);
    if (tid == 0 && half == 0) drow[NN] = pc2;
    float ub  = __ldg(u + b);
    float ndv = fabsf(__ldg(ndec));
    float il  = inl[n];

    __syncthreads();

    const int r_loc = tid >> 5;
    const int i_up = (r_loc + 2) * 32 + lane;
    const int i_dn = r_loc * 32 + lane;
    const int i_ct = (r_loc + 1) * 32 + lane;
    const int lrt = (lane + 1)  & 31;
    const int llf = (lane + 31) & 31;

    float ctr[16];
    #pragma unroll
    for (int p = 0; p < 16; p++) ctr[p] = s[p * HSTR + i_ct];

    float psum = 0.0f;
    #pragma unroll
    for (int p = 0; p < 16; p++) {
        const float* sp = s + p * HSTR;
        float up = sp[i_up];
        float dn = sp[i_dn];
        float rt = __shfl_sync(0xffffffffu, ctr[p], lrt);
        float lf = __shfl_sync(0xffffffffu, ctr[p], llf);
        float lap = up + dn + rt + lf - 4.0f * ctr[p];
        psum += ctr[p] * sA[p];
        float d = sP[p] * f - sDe[p] * ctr[p] + sD[p] * lap;
        ctr[p] = fmaf(d, DTc, ctr[p]);
    }
    float dn_part = psum * pc2 - nm * ndv + il * ub;
    // Pre-multiplied by ablate; k2 atomically adds DT*C*abl.
    drow[NEU_OFF + n] = (nm + dn_part * DTc) * abl;

    __syncthreads();
    #pragma unroll
    for (int p = 0; p < 16; p++) s[p * HSTR + i_ct] = ctr[p];
    __syncthreads();

    // --- Write back slab region ---
    if (tid < h) {
        int l = tid;
        __stcs(drow + PEP_OFF + gbase + l, s[(l & 15) * HSTR + 32 + (l >> 4)]);
    }
    if (tid < t4) {
        int l = 8192 - t4 + tid;
        __stcs(drow + PEP_OFF + gbase + l, s[(l & 15) * HSTR + 32 + (l >> 4)]);
    }
    {
        float4* __restrict__ dst4 = (float4*)(drow + PEP_OFF + gbase + h);
        #pragma unroll
        for (int i = tid; i < N4; i += K1T) {
            int l = h + 4 * i;
            float4 v;
            v.x = s[((l + 0) & 15) * HSTR + 32 + ((l + 0) >> 4)];
            v.y = s[((l + 1) & 15) * HSTR + 32 + ((l + 1) >> 4)];
            v.z = s[((l + 2) & 15) * HSTR + 32 + ((l + 2) >> 4)];
            v.w = s[((l + 3) & 15) * HSTR + 32 + ((l + 3) >> 4)];
            __stcs(dst4 + i, v);
        }
    }
}

// ---------------------------------------------------------------------------
// Kernel 2 (R11-exact): split-K bf16 GEMM, KSPLIT=2. Grid (16, 32, 2) = 1024
// CTAs (~6.9/SM, one full resident wave). Each CTA: BM=64 x BN=64 tile over a
// K half (8 k64-tiles), 128 threads, 4 warps (2m x 2n), 2-stage cp.async
// (32 KB smem -> 7 CTAs/SM resident).
// Epilogue: atomicAdd(DT * C_part * ablate) into the pre-scaled neuron slot.
// ---------------------------------------------------------------------------
#define BM 64
#define BN 64
#define BKH 64
#define KSPLIT 2
#define KITERS (NN / BKH / KSPLIT)   // 8
#define STAGES 2

#define A_TILE_BYTES (BM * BKH * 2)   // 8192
#define B_TILE_BYTES (BKH * BN * 2)   // 8192
#define SMEM_K2 (STAGES * (A_TILE_BYTES + B_TILE_BYTES))  // 32768

__device__ __forceinline__ void cpa16(uint32_t s, const void* g) {
    asm volatile("cp.async.cg.shared.global [%0], [%1], 16;" :: "r"(s), "l"(g));
}
#define CP_COMMIT() asm volatile("cp.async.commit_group;")
#define CP_WAIT(n)  asm volatile("cp.async.wait_group %0;" :: "n"(n))

__device__ __forceinline__ void ldsm4(uint32_t& r0, uint32_t& r1, uint32_t& r2,
                                      uint32_t& r3, uint32_t a) {
    asm volatile("ldmatrix.sync.aligned.m8n8.x4.shared.b16 {%0,%1,%2,%3}, [%4];"
                 : "=r"(r0), "=r"(r1), "=r"(r2), "=r"(r3) : "r"(a));
}
__device__ __forceinline__ void ldsm4t(uint32_t& r0, uint32_t& r1, uint32_t& r2,
                                       uint32_t& r3, uint32_t a) {
    asm volatile("ldmatrix.sync.aligned.m8n8.x4.trans.shared.b16 {%0,%1,%2,%3}, [%4];"
                 : "=r"(r0), "=r"(r1), "=r"(r2), "=r"(r3) : "r"(a));
}
__device__ __forceinline__ void mma16(float* c, const uint32_t* a, const uint32_t* b) {
    asm volatile(
        "mma.sync.aligned.m16n8k16.row.col.f32.bf16.bf16.f32 "
        "{%0,%1,%2,%3}, {%4,%5,%6,%7}, {%8,%9}, {%0,%1,%2,%3};"
        : "+f"(c[0]), "+f"(c[1]), "+f"(c[2]), "+f"(c[3])
        : "r"(a[0]), "r"(a[1]), "r"(a[2]), "r"(a[3]), "r"(b[0]), "r"(b[1]));
}

__device__ __forceinline__ uint32_t swz(int row, int c) {
    return (uint32_t)(row * 128 + ((c ^ (row & 7)) << 4));
}

extern "C" __global__ void __launch_bounds__(128)
k2_gemm(const float* __restrict__ state, float* __restrict__ snew)
{
    extern __shared__ __align__(16) unsigned char dsm[];
    const uint32_t sbase = (uint32_t)__cvta_generic_to_shared(dsm);
    const uint32_t sA = sbase;                          // [STAGES][A_TILE_BYTES]
    const uint32_t sB = sbase + STAGES * A_TILE_BYTES;  // [STAGES][B_TILE_BYTES]

    const int tid  = threadIdx.x;
    const int lane = tid & 31;
    const int warp = tid >> 5;
    const int wm = warp >> 1, wn = warp & 1;
    const int l15 = lane & 15, l16 = lane >> 4;
    const int m0 = blockIdx.y * BM;
    const int n0 = blockIdx.x * BN;
    const int k0 = blockIdx.z * (NN / KSPLIT);    // K half base

    const __nv_bfloat16* __restrict__ gA = g_Abf;
    const __nv_bfloat16* __restrict__ gB = g_Bbf;

    const int sr = tid >> 3;     // 0..15
    const int sc = tid & 7;      // 16B chunk within 128B row

    float acc[2][4][4];
    #pragma unroll
    for (int i = 0; i < 2; i++)
        #pragma unroll
        for (int j = 0; j < 4; j++)
            #pragma unroll
            for (int k = 0; k < 4; k++) acc[i][j][k] = 0.0f;

    auto stage = [&](int kt) {
        const int buf = kt & 1;
        const int kh = k0 + kt * BKH;
        uint32_t aB = sA + buf * A_TILE_BYTES;
        #pragma unroll
        for (int i = 0; i < 4; i++) {
            int row = sr + i * 16;
            cpa16(aB + swz(row, sc), gA + (size_t)(m0 + row) * NN + kh + sc * 8);
        }
        uint32_t bB = sB + buf * B_TILE_BYTES;
        #pragma unroll
        for (int i = 0; i < 4; i++) {
            int row = sr + i * 16;
            cpa16(bB + swz(row, sc), gB + (size_t)(kh + row) * NN + n0 + sc * 8);
        }
    };

    stage(0); CP_COMMIT();

    for (int kt = 0; kt < KITERS; kt++) {
        CP_WAIT(0);
        __syncthreads();                 // buffer kt&1 ready; prev reads done

        if (kt + 1 < KITERS) { stage(kt + 1); CP_COMMIT(); }

        const int cur = kt & 1;
        const uint32_t aB = sA + cur * A_TILE_BYTES;
        const uint32_t bB = sB + cur * B_TILE_BYTES;

        #pragma unroll
        for (int s = 0; s < 4; s++) {               // 4 k16 steps per BK=64
            uint32_t a[2][4];
            #pragma unroll
            for (int sm = 0; sm < 2; sm++) {
                int row = wm * 32 + sm * 16 + l15;
                int ch  = 2 * s + l16;
                ldsm4(a[sm][0], a[sm][1], a[sm][2], a[sm][3], aB + swz(row, ch));
            }
            uint32_t bq[2][4];
            #pragma unroll
            for (int nt = 0; nt < 2; nt++) {
                int row = 16 * s + l15;
                int ch  = wn * 4 + nt * 2 + l16;
                ldsm4t(bq[nt][0], bq[nt][1], bq[nt][2], bq[nt][3], bB + swz(row, ch));
            }
            #pragma unroll
            for (int sm = 0; sm < 2; sm++)
                #pragma unroll
                for (int j = 0; j < 4; j++) {
                    uint32_t bp[2] = { bq[j >> 1][(j & 1) * 2],
                                       bq[j >> 1][(j & 1) * 2 + 1] };
                    mma16(acc[sm][j], a[sm], bp);
                }
        }
        __syncthreads();                 // all reads of cur done before restage
    }

    // ---- split-K epilogue: atomicAdd(DT * C_part * ablate) ----
    const int g = lane >> 2, t = lane & 3;
    #pragma unroll
    for (int sm = 0; sm < 2; sm++) {
        #pragma unroll
        for (int j = 0; j < 4; j++) {
            int row0 = m0 + wm * 32 + sm * 16 + g;
            int col0 = n0 + wn * 32 + j * 8 + 2 * t;
            #pragma unroll
            for (int hh = 0; hh < 2; hh++) {
                int m = row0 + hh * 8;
                size_t off = (size_t)m * SSZ;
                #pragma unroll
                for (int q = 0; q < 2; q++) {
                    int nn = col0 + q;
                    float cc  = acc[sm][j][hh * 2 + q];
                    float abl = state[off + nn];
                    atomicAdd(snew + off + NEU_OFF + nn, DTc * cc * abl);
                }
            }
        }
    }
}

// ---------------------------------------------------------------------------
extern "C" void kernel_launch(void* const* d_in, const int* in_sizes, int n_in,
                              void* d_out, int out_size) {
    const float* u      = (const float*)d_in[0];
    const float* state  = (const float*)d_in[1];
    const float* noise  = (const float*)d_in[2];
    const float* D      = (const float*)d_in[3];
    const float* prodr  = (const float*)d_in[4];
    const float* decayr = (const float*)d_in[5];
    const float* act    = (const float*)d_in[6];
    const float* syn    = (const float*)d_in[7];
    const float* ndec   = (const float*)d_in[8];
    const float* inl    = (const float*)d_in[9];

    float* out   = (float*)d_out;
    float* out_f = out;                         // firing [2048,1024]
    float* snew  = out + (size_t)NB * NN;       // state_new [2048,18433]

    const int smem1 = 16 * HSTR * sizeof(float);
    cudaFuncSetAttribute(k1_kernel, cudaFuncAttributeMaxDynamicSharedMemorySize, smem1);
    k1_kernel<<<2 * NB, K1T, smem1>>>(u, state, noise, D, prodr, decayr, act,
                                      ndec, inl, syn, out_f, snew);

    cudaFuncSetAttribute(k2_gemm, cudaFuncAttributeMaxDynamicSharedMemorySize, SMEM_K2);
    dim3 grid(NN / BN, NB / BM, KSPLIT);
    k2_gemm<<<grid, 128, SMEM_K2>>>(state, snew);
}